// round 14
// baseline (speedup 1.0000x reference)
#include <cuda_runtime.h>
#include <cuda_bf16.h>
#include <math.h>
#include <stdint.h>

#define BB 64      // batch
#define TT 512     // seq len
#define DD 512     // input size
#define HH 1024    // hidden
#define G4 4096    // 4*HH
#define NBLK 128   // persistent blocks (1/SM, co-resident)

// ---------------- scratch (static __device__, no allocs) ----------------
__device__ float g_G[(size_t)TT * BB * G4];
__device__ uint32_t g_Ubhi0[(size_t)NBLK * 32 * 512];  // [blk][n32][kp512]
__device__ uint32_t g_Ublo0[(size_t)NBLK * 32 * 512];
__device__ uint32_t g_Ubhi1[(size_t)NBLK * 32 * 512];
__device__ uint32_t g_Ublo1[(size_t)NBLK * 32 * 512];
__device__ uint32_t g_hbf[2 * 2 * BB * 512];           // [plane][ping][b][kp]
// bf16x2 planes for the big GEMMs
__device__ uint32_t g_Xhi[(size_t)BB * TT * 256];      // [b*T+t][kp256]
__device__ uint32_t g_Xlo[(size_t)BB * TT * 256];
__device__ uint32_t g_Whi0[(size_t)G4 * 256];          // [n][kp256]
__device__ uint32_t g_Wlo0[(size_t)G4 * 256];
__device__ uint32_t g_Whi1[(size_t)G4 * 512];          // [n][kp512]
__device__ uint32_t g_Wlo1[(size_t)G4 * 512];
__device__ uint32_t g_Hshi[(size_t)TT * BB * 512];     // [t*B+b][kp512]
__device__ uint32_t g_Hslo[(size_t)TT * BB * 512];

// ---------------- two-level tree grid barrier (validated R13) ----------------
__device__ unsigned g_c1[16 * 32];
__device__ unsigned g_croot = 0;
__device__ volatile unsigned g_gen = 0;

__device__ __forceinline__ void grid_barrier() {
    __syncthreads();
    if (threadIdx.x == 0) {
        __threadfence();
        unsigned old = g_gen;
        unsigned grp = blockIdx.x >> 3;
        if (atomicAdd(&g_c1[grp * 32], 1u) == 7u) {
            g_c1[grp * 32] = 0;
            __threadfence();
            if (atomicAdd(&g_croot, 1u) == 15u) {
                g_croot = 0;
                __threadfence();
                g_gen = old + 1;
            }
        }
        while (g_gen == old) { }
        __threadfence();
    }
    __syncthreads();
}

__device__ __forceinline__ float d_sigmoid(float x) { return 1.0f / (1.0f + expf(-x)); }
__device__ __forceinline__ float d_tanh(float x)    { return 1.0f - 2.0f / (expf(2.0f * x) + 1.0f); }

// ---------------- bf16 helpers ----------------
__device__ __forceinline__ void mma16bf(float* c, const uint32_t* a, const uint32_t* b) {
    asm volatile("mma.sync.aligned.m16n8k16.row.col.f32.bf16.bf16.f32 "
        "{%0,%1,%2,%3}, {%4,%5,%6,%7}, {%8,%9}, {%0,%1,%2,%3};\n"
        : "+f"(c[0]), "+f"(c[1]), "+f"(c[2]), "+f"(c[3])
        : "r"(a[0]), "r"(a[1]), "r"(a[2]), "r"(a[3]), "r"(b[0]), "r"(b[1]));
}
__device__ __forceinline__ void pack_hl(float a, float b, uint32_t& hi, uint32_t& lo) {
    __nv_bfloat16 ah = __float2bfloat16_rn(a);
    __nv_bfloat16 bh = __float2bfloat16_rn(b);
    __nv_bfloat16 al = __float2bfloat16_rn(a - __bfloat162float(ah));
    __nv_bfloat16 bl = __float2bfloat16_rn(b - __bfloat162float(bh));
    hi = (uint32_t)*(uint16_t*)&ah | ((uint32_t)*(uint16_t*)&bh << 16);
    lo = (uint32_t)*(uint16_t*)&al | ((uint32_t)*(uint16_t*)&bl << 16);
}

// ---------------- pack kernels ----------------
// U pack (validated): [blk][n32][kp512]
__global__ void packUbf16(const float* __restrict__ U,
                          uint32_t* __restrict__ Uhi, uint32_t* __restrict__ Ulo) {
    int e = blockIdx.x * blockDim.x + threadIdx.x;
    if (e >= NBLK * 32 * 512) return;
    int kp  = e & 511;
    int n   = (e >> 9) & 31;
    int blk = e >> 14;
    int g = n >> 3, u = n & 7;
    int col = g * HH + blk * 8 + u;
    uint32_t hi, lo;
    pack_hl(U[(size_t)(2 * kp) * G4 + col], U[(size_t)(2 * kp + 1) * G4 + col], hi, lo);
    Uhi[e] = hi; Ulo[e] = lo;
}
// row-major fp32 [rows][K] -> planes [row][kp]
__global__ void packRows(const float* __restrict__ S, uint32_t* __restrict__ Phi,
                         uint32_t* __restrict__ Plo, int total) {
    int e = blockIdx.x * blockDim.x + threadIdx.x;   // e = row*Kp + kp, K contiguous
    if (e >= total) return;
    uint32_t hi, lo;
    pack_hl(S[2 * e], S[2 * e + 1], hi, lo);
    Phi[e] = hi; Plo[e] = lo;
}
// W [K][4096] -> planes [n][kp]
__global__ void packW(const float* __restrict__ W, uint32_t* __restrict__ Phi,
                      uint32_t* __restrict__ Plo, int Kp) {
    int e = blockIdx.x * blockDim.x + threadIdx.x;
    if (e >= G4 * Kp) return;
    int kp = e % Kp, n = e / Kp;
    uint32_t hi, lo;
    pack_hl(W[(size_t)(2 * kp) * G4 + n], W[(size_t)(2 * kp + 1) * G4 + n], hi, lo);
    Phi[e] = hi; Plo[e] = lo;
}

// ---------------- bf16x3 big GEMM, pre-split planes ----------------
// C[m][n] = A[rowmap(m)] @ B[n] + bias[n]; block 128x64, 16 kp (=32 k) per iter.
#define A_STR 20
#define B_STR 20
#define A_PL (128 * A_STR)
#define B_PL (64 * B_STR)
#define GBUF (2 * A_PL + 2 * B_PL)
#define GSMEM (2 * GBUF * 4)

__global__ __launch_bounds__(256, 2) void gemm_bf16(
    const uint32_t* __restrict__ Ahi, const uint32_t* __restrict__ Alo,
    const uint32_t* __restrict__ Bhi, const uint32_t* __restrict__ Blo,
    const float* __restrict__ bias, float* __restrict__ C,
    int Kp, int rsA, int mode)
{
    extern __shared__ uint32_t sm[];
    int tid = threadIdx.x;
    int lane = tid & 31, wid = tid >> 5;
    int wm = wid & 3, wn = wid >> 2;
    int t4 = lane & 3, g8 = lane >> 2;
    int m0 = blockIdx.y * 128, n0 = blockIdx.x * 64;

    // A staging: 2 uint4 slots per plane per thread
    const uint32_t* pAhi[2];
    const uint32_t* pAlo[2];
    int amS[2], aqS[2];
#pragma unroll
    for (int j = 0; j < 2; j++) {
        int s = tid + j * 256;          // 0..511
        int m = s >> 2, q = s & 3;
        amS[j] = m; aqS[j] = q;
        int gm = m0 + m;
        size_t row = (mode == 0) ? (size_t)(gm & 63) * TT + (gm >> 6) : (size_t)gm;
        pAhi[j] = Ahi + row * rsA + q * 4;
        pAlo[j] = Alo + row * rsA + q * 4;
    }
    // B staging: 1 uint4 slot per plane per thread
    int bnS = tid >> 2, bqS = tid & 3;
    const uint32_t* pBhi = Bhi + (size_t)(n0 + bnS) * Kp + bqS * 4;
    const uint32_t* pBlo = Blo + (size_t)(n0 + bnS) * Kp + bqS * 4;

    uint4 ra_hi[2], ra_lo[2], rb_hi, rb_lo;
#pragma unroll
    for (int j = 0; j < 2; j++) {
        ra_hi[j] = *(const uint4*)pAhi[j];
        ra_lo[j] = *(const uint4*)pAlo[j];
    }
    rb_hi = *(const uint4*)pBhi;
    rb_lo = *(const uint4*)pBlo;

    float acc[2][4][4];
#pragma unroll
    for (int mt = 0; mt < 2; mt++)
#pragma unroll
        for (int nt = 0; nt < 4; nt++)
#pragma unroll
            for (int i = 0; i < 4; i++) acc[mt][nt][i] = 0.0f;

    int nIter = Kp / 16;
    for (int it = 0; it < nIter; it++) {
        uint32_t* base = sm + (it & 1) * GBUF;
        uint32_t* ahi = base;
        uint32_t* alo = base + A_PL;
        uint32_t* bhi = base + 2 * A_PL;
        uint32_t* blo = bhi + B_PL;

#pragma unroll
        for (int j = 0; j < 2; j++) {
            *(uint4*)&ahi[amS[j] * A_STR + aqS[j] * 4] = ra_hi[j];
            *(uint4*)&alo[amS[j] * A_STR + aqS[j] * 4] = ra_lo[j];
        }
        *(uint4*)&bhi[bnS * B_STR + bqS * 4] = rb_hi;
        *(uint4*)&blo[bnS * B_STR + bqS * 4] = rb_lo;
        __syncthreads();

        if (it + 1 < nIter) {
#pragma unroll
            for (int j = 0; j < 2; j++) {
                pAhi[j] += 16; pAlo[j] += 16;
                ra_hi[j] = *(const uint4*)pAhi[j];
                ra_lo[j] = *(const uint4*)pAlo[j];
            }
            pBhi += 16; pBlo += 16;
            rb_hi = *(const uint4*)pBhi;
            rb_lo = *(const uint4*)pBlo;
        }

#pragma unroll
        for (int ks = 0; ks < 2; ks++) {
            int ko = ks * 8 + t4;
            uint32_t Ah[2][4], Al[2][4];
#pragma unroll
            for (int mt = 0; mt < 2; mt++) {
                int r = (wm * 32 + mt * 16 + g8) * A_STR;
                Ah[mt][0] = ahi[r + ko];
                Ah[mt][1] = ahi[r + 8 * A_STR + ko];
                Ah[mt][2] = ahi[r + ko + 4];
                Ah[mt][3] = ahi[r + 8 * A_STR + ko + 4];
                Al[mt][0] = alo[r + ko];
                Al[mt][1] = alo[r + 8 * A_STR + ko];
                Al[mt][2] = alo[r + ko + 4];
                Al[mt][3] = alo[r + 8 * A_STR + ko + 4];
            }
#pragma unroll
            for (int nt = 0; nt < 4; nt++) {
                int nr = (wn * 32 + nt * 8 + g8) * B_STR;
                uint32_t Bh[2] = { bhi[nr + ko], bhi[nr + ko + 4] };
                uint32_t Bl[2] = { blo[nr + ko], blo[nr + ko + 4] };
#pragma unroll
                for (int mt = 0; mt < 2; mt++) {
                    mma16bf(acc[mt][nt], Ah[mt], Bh);
                    mma16bf(acc[mt][nt], Al[mt], Bh);
                    mma16bf(acc[mt][nt], Ah[mt], Bl);
                }
            }
        }
    }

#pragma unroll
    for (int mt = 0; mt < 2; mt++)
#pragma unroll
        for (int nt = 0; nt < 4; nt++) {
            int gr = m0 + wm * 32 + mt * 16 + g8;
            int gc = n0 + wn * 32 + nt * 8 + 2 * t4;
            float bz0 = bias[gc], bz1 = bias[gc + 1];
            float2 v0 = make_float2(acc[mt][nt][0] + bz0, acc[mt][nt][1] + bz1);
            float2 v1 = make_float2(acc[mt][nt][2] + bz0, acc[mt][nt][3] + bz1);
            *(float2*)&C[(size_t)gr * G4 + gc] = v0;
            *(float2*)&C[(size_t)(gr + 8) * G4 + gc] = v1;
        }
}

// ---------------- persistent recurrent layer (R13 + dbl-buffer + dual acc) --
// 256 thr, 8 warps, warp tile m16n16. 8 chunks of 64 kp, double-buffered h
// staging (1 sync/chunk). Layer 0 writes hseq bf16 planes; layer 1 writes fp32.
#define SM_UHI 0                          // [32][516]
#define SM_ULO 16512
#define SM_H   33024                      // 2 bufs x (HHI 4352 + HLO 4352)
#define HBUFS  8704
#define SM_CS  50432                      // [64][34] f32
#define SM_TOT ((50432 + 64 * 34) * 4)    // 210432 bytes
#define USTR 516
#define HSTR 68
#define CSTR 34

__global__ __launch_bounds__(256, 1) void lstm_mma(
    const float* __restrict__ Gbase,
    const uint32_t* __restrict__ Ubhi,
    const uint32_t* __restrict__ Ublo,
    const float* __restrict__ h0,
    const float* __restrict__ c0,
    uint32_t* __restrict__ hpp,
    uint32_t* __restrict__ hseqhi,        // layer0: bf16 plane out (else null)
    uint32_t* __restrict__ hseqlo,
    float* __restrict__ seq_out,          // layer1: fp32 out at [b*T*H + t*H + u]
    float* hT, float* cT)
{
    extern __shared__ uint32_t sm[];
    float* smf = (float*)sm;
    int tid = threadIdx.x;
    int lane = tid & 31, wid = tid >> 5;
    int wm = wid & 3, wn = wid >> 2;
    int t4 = lane & 3, g8 = lane >> 2;
    int blk = blockIdx.x;

    // ---- load U slice (once) ----
    {
        const float4* shi = (const float4*)(Ubhi + (size_t)blk * 32 * 512);
        const float4* slo = (const float4*)(Ublo + (size_t)blk * 32 * 512);
#pragma unroll
        for (int i = 0; i < 16; i++) {
            int f = tid + i * 256;
            int n = f >> 7, c = f & 127;
            *(float4*)&sm[SM_UHI + n * USTR + c * 4] = shi[f];
            *(float4*)&sm[SM_ULO + n * USTR + c * 4] = slo[f];
        }
    }

    // ---- init h planes (ping 0) ----
    for (int slot = blk * 256 + tid; slot < BB * 512; slot += NBLK * 256) {
        int b = slot >> 9, kp = slot & 511;
        uint32_t hi, lo;
        pack_hl(h0[b * HH + 2 * kp], h0[b * HH + 2 * kp + 1], hi, lo);
        hpp[0 * 65536 + 0 * 32768 + slot] = hi;
        hpp[1 * 65536 + 0 * 32768 + slot] = lo;
    }
    int ju = tid & 3, bg = tid >> 2;
    int u0g = blk * 8 + 2 * ju;
    int kp_own = blk * 4 + ju;
    float cE = c0[bg * HH + u0g], cO = c0[bg * HH + u0g + 1];

    // staging map: 4 float4 per plane per chunk (64 rows x 16 float4)
    int srow[4], scol[4];
#pragma unroll
    for (int j = 0; j < 4; j++) {
        int f = tid + j * 256;
        srow[j] = f >> 4;
        scol[j] = f & 15;
    }
    int r0 = 16 * wm + g8;

    for (int t = 0; t < TT; t++) {
        // ---- prefetch G accumulators BEFORE barrier ----
        const float* Gt = Gbase + (size_t)t * BB * G4;
        float acc[2][4], acc2[2][4];
#pragma unroll
        for (int nt = 0; nt < 2; nt++) {
            int gcol = (2 * wn + nt) * HH + blk * 8 + 2 * t4;
            float2 v0 = *(const float2*)&Gt[(size_t)r0 * G4 + gcol];
            float2 v1 = *(const float2*)&Gt[(size_t)(r0 + 8) * G4 + gcol];
            acc[nt][0] = v0.x; acc[nt][1] = v0.y;
            acc[nt][2] = v1.x; acc[nt][3] = v1.y;
            acc2[nt][0] = acc2[nt][1] = acc2[nt][2] = acc2[nt][3] = 0.0f;
        }

        grid_barrier();

        const uint32_t* hin_hi = hpp + 0 * 65536 + (t & 1) * 32768;
        const uint32_t* hin_lo = hpp + 1 * 65536 + (t & 1) * 32768;
        uint32_t* hout_hi = hpp + 0 * 65536 + ((t + 1) & 1) * 32768;
        uint32_t* hout_lo = hpp + 1 * 65536 + ((t + 1) & 1) * 32768;

        // prefetch chunk 0
        float4 rhi[4], rlo[4];
#pragma unroll
        for (int j = 0; j < 4; j++) {
            rhi[j] = ((const float4*)(hin_hi + srow[j] * 512))[scol[j]];
            rlo[j] = ((const float4*)(hin_lo + srow[j] * 512))[scol[j]];
        }

        for (int kc = 0; kc < 8; kc++) {
            uint32_t hb = SM_H + (kc & 1) * HBUFS;
            // store staged regs into this chunk's buffer
#pragma unroll
            for (int j = 0; j < 4; j++) {
                *(float4*)&sm[hb + srow[j] * HSTR + scol[j] * 4] = rhi[j];
                *(float4*)&sm[hb + 4352 + srow[j] * HSTR + scol[j] * 4] = rlo[j];
            }
            __syncthreads();   // single sync: buf visible; old buf (kc-2) free
            // prefetch next chunk (chunk stride = 64 u32)
            if (kc < 7) {
#pragma unroll
                for (int j = 0; j < 4; j++) {
                    rhi[j] = ((const float4*)(hin_hi + srow[j] * 512 + (kc + 1) * 64))[scol[j]];
                    rlo[j] = ((const float4*)(hin_lo + srow[j] * 512 + (kc + 1) * 64))[scol[j]];
                }
            }
            // 8 x k16 mma (dual accumulators)
#pragma unroll
            for (int kk = 0; kk < 8; kk++) {
                int ko = kk * 8 + t4;
                int ku = kc * 64 + ko;
                uint32_t Ah[4], Al[4];
                Ah[0] = sm[hb + r0 * HSTR + ko];
                Ah[1] = sm[hb + (r0 + 8) * HSTR + ko];
                Ah[2] = sm[hb + r0 * HSTR + ko + 4];
                Ah[3] = sm[hb + (r0 + 8) * HSTR + ko + 4];
                Al[0] = sm[hb + 4352 + r0 * HSTR + ko];
                Al[1] = sm[hb + 4352 + (r0 + 8) * HSTR + ko];
                Al[2] = sm[hb + 4352 + r0 * HSTR + ko + 4];
                Al[3] = sm[hb + 4352 + (r0 + 8) * HSTR + ko + 4];
#pragma unroll
                for (int nt = 0; nt < 2; nt++) {
                    int n = 16 * wn + nt * 8 + g8;
                    uint32_t Bh[2] = { sm[SM_UHI + n * USTR + ku], sm[SM_UHI + n * USTR + ku + 4] };
                    uint32_t Bl[2] = { sm[SM_ULO + n * USTR + ku], sm[SM_ULO + n * USTR + ku + 4] };
                    mma16bf(acc[nt], Ah, Bh);
                    mma16bf(acc2[nt], Al, Bh);
                    mma16bf(acc2[nt], Ah, Bl);
                }
            }
        }
        __syncthreads();   // last buffer reads done before Cs overwrite below

        // ---- C frags -> smem ----
#pragma unroll
        for (int nt = 0; nt < 2; nt++) {
            int nc = 16 * wn + nt * 8 + 2 * t4;
            smf[SM_CS + r0 * CSTR + nc]           = acc[nt][0] + acc2[nt][0];
            smf[SM_CS + r0 * CSTR + nc + 1]       = acc[nt][1] + acc2[nt][1];
            smf[SM_CS + (r0 + 8) * CSTR + nc]     = acc[nt][2] + acc2[nt][2];
            smf[SM_CS + (r0 + 8) * CSTR + nc + 1] = acc[nt][3] + acc2[nt][3];
        }
        __syncthreads();

        // ---- elementwise: thread = (bg, ju) ----
        {
            const float* crow = smf + SM_CS + bg * CSTR;
            float2 gi = *(const float2*)&crow[0 * 8 + 2 * ju];
            float2 gf = *(const float2*)&crow[1 * 8 + 2 * ju];
            float2 gg = *(const float2*)&crow[2 * 8 + 2 * ju];
            float2 go = *(const float2*)&crow[3 * 8 + 2 * ju];

            float cnE = d_sigmoid(gf.x) * cE + d_sigmoid(gi.x) * d_tanh(gg.x);
            float cnO = d_sigmoid(gf.y) * cO + d_sigmoid(gi.y) * d_tanh(gg.y);
            float hnE = d_sigmoid(go.x) * d_tanh(cnE);
            float hnO = d_sigmoid(go.y) * d_tanh(cnO);
            cE = cnE; cO = cnO;

            uint32_t hi, lo;
            pack_hl(hnE, hnO, hi, lo);
            int slot = bg * 512 + kp_own;
            hout_hi[slot] = hi;
            hout_lo[slot] = lo;

            if (hseqhi) {
                // layer 0: bf16 planes, row = t*B + bg
                size_t r = ((size_t)t * BB + bg) * 512 + kp_own;
                hseqhi[r] = hi;
                hseqlo[r] = lo;
            } else {
                // layer 1: fp32 out[b][t][u]
                *(float2*)&seq_out[((size_t)bg * TT + t) * HH + u0g] =
                    make_float2(hnE, hnO);
                if (t == TT - 1 && hT) {
                    int hidx = bg * HH + u0g;
                    *(float2*)&hT[hidx] = make_float2(hnE, hnO);
                    *(float2*)&cT[hidx] = make_float2(cnE, cnO);
                }
            }
        }
        // next grid_barrier's __syncthreads protects Cs reuse
    }
}

// ---------------- launch ----------------
extern "C" void kernel_launch(void* const* d_in, const int* in_sizes, int n_in,
                              void* d_out, int out_size)
{
    const float* X  = (const float*)d_in[0];
    const float* h0 = (const float*)d_in[1];
    const float* c0 = (const float*)d_in[2];
    const float* W0 = (const float*)d_in[3];
    const float* U0 = (const float*)d_in[4];
    const float* b0 = (const float*)d_in[5];
    const float* W1 = (const float*)d_in[6];
    const float* U1 = (const float*)d_in[7];
    const float* b1 = (const float*)d_in[8];
    float* out = (float*)d_out;

    float *G;
    uint32_t *Uh0, *Ul0, *Uh1, *Ul1, *hbf;
    uint32_t *Xhi, *Xlo, *Wh0, *Wl0, *Wh1, *Wl1, *Hshi, *Hslo;
    cudaGetSymbolAddress((void**)&G,    g_G);
    cudaGetSymbolAddress((void**)&Uh0,  g_Ubhi0);
    cudaGetSymbolAddress((void**)&Ul0,  g_Ublo0);
    cudaGetSymbolAddress((void**)&Uh1,  g_Ubhi1);
    cudaGetSymbolAddress((void**)&Ul1,  g_Ublo1);
    cudaGetSymbolAddress((void**)&hbf,  g_hbf);
    cudaGetSymbolAddress((void**)&Xhi,  g_Xhi);
    cudaGetSymbolAddress((void**)&Xlo,  g_Xlo);
    cudaGetSymbolAddress((void**)&Wh0,  g_Whi0);
    cudaGetSymbolAddress((void**)&Wl0,  g_Wlo0);
    cudaGetSymbolAddress((void**)&Wh1,  g_Whi1);
    cudaGetSymbolAddress((void**)&Wl1,  g_Wlo1);
    cudaGetSymbolAddress((void**)&Hshi, g_Hshi);
    cudaGetSymbolAddress((void**)&Hslo, g_Hslo);

    cudaFuncSetAttribute(gemm_bf16, cudaFuncAttributeMaxDynamicSharedMemorySize, GSMEM);
    cudaFuncSetAttribute(lstm_mma,  cudaFuncAttributeMaxDynamicSharedMemorySize, SM_TOT);

    // pack weights / inputs into bf16 hi/lo planes
    packUbf16<<<(NBLK * 32 * 512) / 256, 256>>>(U0, Uh0, Ul0);
    packUbf16<<<(NBLK * 32 * 512) / 256, 256>>>(U1, Uh1, Ul1);
    packRows<<<(BB * TT * 256) / 256, 256>>>(X, Xhi, Xlo, BB * TT * 256);
    packW<<<(G4 * 256) / 256, 256>>>(W0, Wh0, Wl0, 256);
    packW<<<(G4 * 512) / 256, 256>>>(W1, Wh1, Wl1, 512);

    dim3 ggrid(G4 / 64, (TT * BB) / 128);   // (64, 256)

    bool wantHC = (size_t)out_size >= (size_t)BB * TT * HH + 2ull * BB * HH;
    float* hT = wantHC ? out + (size_t)BB * TT * HH : nullptr;
    float* cT = wantHC ? hT + (size_t)BB * HH : nullptr;

    // ---- layer 0 ----
    gemm_bf16<<<ggrid, 256, GSMEM>>>(Xhi, Xlo, Wh0, Wl0, b0, G, 256, 256, 0);
    lstm_mma<<<NBLK, 256, SM_TOT>>>(G, Uh0, Ul0, h0, c0, hbf,
                                    Hshi, Hslo, nullptr,
                                    nullptr, nullptr);

    // ---- layer 1 ----
    gemm_bf16<<<ggrid, 256, GSMEM>>>(Hshi, Hslo, Wh1, Wl1, b1, G, 512, 512, 1);
    lstm_mma<<<NBLK, 256, SM_TOT>>>(G, Uh1, Ul1,
                                    h0 + (size_t)BB * HH, c0 + (size_t)BB * HH,
                                    hbf,
                                    nullptr, nullptr, out,
                                    hT, cT);
}

// round 15
// speedup vs baseline: 1.0702x; 1.0702x over previous
#include <cuda_runtime.h>
#include <cuda_bf16.h>
#include <math.h>
#include <stdint.h>

#define BB 64      // batch
#define TT 512     // seq len
#define DD 512     // input size
#define HH 1024    // hidden
#define G4 4096    // 4*HH
#define NBLK 128   // persistent blocks (1/SM, co-resident)

// ---------------- scratch (static __device__, no allocs) ----------------
__device__ float g_G[(size_t)TT * BB * G4];
__device__ uint32_t g_Ubhi0[(size_t)NBLK * 32 * 512];  // [blk][n32][kp512]
__device__ uint32_t g_Ublo0[(size_t)NBLK * 32 * 512];
__device__ uint32_t g_Ubhi1[(size_t)NBLK * 32 * 512];
__device__ uint32_t g_Ublo1[(size_t)NBLK * 32 * 512];
__device__ uint32_t g_hbf[2 * 2 * BB * 512];           // [plane][ping][b][kp]
// bf16x2 planes for the big GEMMs
__device__ uint32_t g_Xhi[(size_t)BB * TT * 256];      // [b*T+t][kp256]
__device__ uint32_t g_Xlo[(size_t)BB * TT * 256];
__device__ uint32_t g_Whi0[(size_t)G4 * 256];          // [n][kp256]
__device__ uint32_t g_Wlo0[(size_t)G4 * 256];
__device__ uint32_t g_Whi1[(size_t)G4 * 512];          // [n][kp512]
__device__ uint32_t g_Wlo1[(size_t)G4 * 512];
__device__ uint32_t g_Hshi[(size_t)TT * BB * 512];     // [t*B+b][kp512]
__device__ uint32_t g_Hslo[(size_t)TT * BB * 512];

// ---------------- two-level tree grid barrier (validated R13) ----------------
__device__ unsigned g_c1[16 * 32];
__device__ unsigned g_croot = 0;
__device__ volatile unsigned g_gen = 0;

__device__ __forceinline__ void grid_barrier() {
    __syncthreads();
    if (threadIdx.x == 0) {
        __threadfence();
        unsigned old = g_gen;
        unsigned grp = blockIdx.x >> 3;
        if (atomicAdd(&g_c1[grp * 32], 1u) == 7u) {
            g_c1[grp * 32] = 0;
            __threadfence();
            if (atomicAdd(&g_croot, 1u) == 15u) {
                g_croot = 0;
                __threadfence();
                g_gen = old + 1;
            }
        }
        while (g_gen == old) { }
        __threadfence();
    }
    __syncthreads();
}

__device__ __forceinline__ float d_sigmoid(float x) { return 1.0f / (1.0f + expf(-x)); }
__device__ __forceinline__ float d_tanh(float x)    { return 1.0f - 2.0f / (expf(2.0f * x) + 1.0f); }

// ---------------- bf16 helpers ----------------
__device__ __forceinline__ void mma16bf(float* c, const uint32_t* a, const uint32_t* b) {
    asm volatile("mma.sync.aligned.m16n8k16.row.col.f32.bf16.bf16.f32 "
        "{%0,%1,%2,%3}, {%4,%5,%6,%7}, {%8,%9}, {%0,%1,%2,%3};\n"
        : "+f"(c[0]), "+f"(c[1]), "+f"(c[2]), "+f"(c[3])
        : "r"(a[0]), "r"(a[1]), "r"(a[2]), "r"(a[3]), "r"(b[0]), "r"(b[1]));
}
__device__ __forceinline__ void pack_hl(float a, float b, uint32_t& hi, uint32_t& lo) {
    __nv_bfloat16 ah = __float2bfloat16_rn(a);
    __nv_bfloat16 bh = __float2bfloat16_rn(b);
    __nv_bfloat16 al = __float2bfloat16_rn(a - __bfloat162float(ah));
    __nv_bfloat16 bl = __float2bfloat16_rn(b - __bfloat162float(bh));
    hi = (uint32_t)*(uint16_t*)&ah | ((uint32_t)*(uint16_t*)&bh << 16);
    lo = (uint32_t)*(uint16_t*)&al | ((uint32_t)*(uint16_t*)&bl << 16);
}

// ---------------- pack kernels ----------------
__global__ void packUbf16(const float* __restrict__ U,
                          uint32_t* __restrict__ Uhi, uint32_t* __restrict__ Ulo) {
    int e = blockIdx.x * blockDim.x + threadIdx.x;
    if (e >= NBLK * 32 * 512) return;
    int kp  = e & 511;
    int n   = (e >> 9) & 31;
    int blk = e >> 14;
    int g = n >> 3, u = n & 7;
    int col = g * HH + blk * 8 + u;
    uint32_t hi, lo;
    pack_hl(U[(size_t)(2 * kp) * G4 + col], U[(size_t)(2 * kp + 1) * G4 + col], hi, lo);
    Uhi[e] = hi; Ulo[e] = lo;
}
__global__ void packRows(const float* __restrict__ S, uint32_t* __restrict__ Phi,
                         uint32_t* __restrict__ Plo, int total) {
    int e = blockIdx.x * blockDim.x + threadIdx.x;
    if (e >= total) return;
    uint32_t hi, lo;
    pack_hl(S[2 * e], S[2 * e + 1], hi, lo);
    Phi[e] = hi; Plo[e] = lo;
}
__global__ void packW(const float* __restrict__ W, uint32_t* __restrict__ Phi,
                      uint32_t* __restrict__ Plo, int Kp) {
    int e = blockIdx.x * blockDim.x + threadIdx.x;
    if (e >= G4 * Kp) return;
    int kp = e % Kp, n = e / Kp;
    uint32_t hi, lo;
    pack_hl(W[(size_t)(2 * kp) * G4 + n], W[(size_t)(2 * kp + 1) * G4 + n], hi, lo);
    Phi[e] = hi; Plo[e] = lo;
}

// ---------------- bf16x3 big GEMM, pre-split planes (R14) ----------------
#define A_STR 20
#define B_STR 20
#define A_PL (128 * A_STR)
#define B_PL (64 * B_STR)
#define GBUF (2 * A_PL + 2 * B_PL)
#define GSMEM (2 * GBUF * 4)

__global__ __launch_bounds__(256, 2) void gemm_bf16(
    const uint32_t* __restrict__ Ahi, const uint32_t* __restrict__ Alo,
    const uint32_t* __restrict__ Bhi, const uint32_t* __restrict__ Blo,
    const float* __restrict__ bias, float* __restrict__ C,
    int Kp, int rsA, int mode)
{
    extern __shared__ uint32_t sm[];
    int tid = threadIdx.x;
    int lane = tid & 31, wid = tid >> 5;
    int wm = wid & 3, wn = wid >> 2;
    int t4 = lane & 3, g8 = lane >> 2;
    int m0 = blockIdx.y * 128, n0 = blockIdx.x * 64;

    const uint32_t* pAhi[2];
    const uint32_t* pAlo[2];
    int amS[2], aqS[2];
#pragma unroll
    for (int j = 0; j < 2; j++) {
        int s = tid + j * 256;
        int m = s >> 2, q = s & 3;
        amS[j] = m; aqS[j] = q;
        int gm = m0 + m;
        size_t row = (mode == 0) ? (size_t)(gm & 63) * TT + (gm >> 6) : (size_t)gm;
        pAhi[j] = Ahi + row * rsA + q * 4;
        pAlo[j] = Alo + row * rsA + q * 4;
    }
    int bnS = tid >> 2, bqS = tid & 3;
    const uint32_t* pBhi = Bhi + (size_t)(n0 + bnS) * Kp + bqS * 4;
    const uint32_t* pBlo = Blo + (size_t)(n0 + bnS) * Kp + bqS * 4;

    uint4 ra_hi[2], ra_lo[2], rb_hi, rb_lo;
#pragma unroll
    for (int j = 0; j < 2; j++) {
        ra_hi[j] = *(const uint4*)pAhi[j];
        ra_lo[j] = *(const uint4*)pAlo[j];
    }
    rb_hi = *(const uint4*)pBhi;
    rb_lo = *(const uint4*)pBlo;

    float acc[2][4][4];
#pragma unroll
    for (int mt = 0; mt < 2; mt++)
#pragma unroll
        for (int nt = 0; nt < 4; nt++)
#pragma unroll
            for (int i = 0; i < 4; i++) acc[mt][nt][i] = 0.0f;

    int nIter = Kp / 16;
    for (int it = 0; it < nIter; it++) {
        uint32_t* base = sm + (it & 1) * GBUF;
        uint32_t* ahi = base;
        uint32_t* alo = base + A_PL;
        uint32_t* bhi = base + 2 * A_PL;
        uint32_t* blo = bhi + B_PL;

#pragma unroll
        for (int j = 0; j < 2; j++) {
            *(uint4*)&ahi[amS[j] * A_STR + aqS[j] * 4] = ra_hi[j];
            *(uint4*)&alo[amS[j] * A_STR + aqS[j] * 4] = ra_lo[j];
        }
        *(uint4*)&bhi[bnS * B_STR + bqS * 4] = rb_hi;
        *(uint4*)&blo[bnS * B_STR + bqS * 4] = rb_lo;
        __syncthreads();

        if (it + 1 < nIter) {
#pragma unroll
            for (int j = 0; j < 2; j++) {
                pAhi[j] += 16; pAlo[j] += 16;
                ra_hi[j] = *(const uint4*)pAhi[j];
                ra_lo[j] = *(const uint4*)pAlo[j];
            }
            pBhi += 16; pBlo += 16;
            rb_hi = *(const uint4*)pBhi;
            rb_lo = *(const uint4*)pBlo;
        }

#pragma unroll
        for (int ks = 0; ks < 2; ks++) {
            int ko = ks * 8 + t4;
            uint32_t Ah[2][4], Al[2][4];
#pragma unroll
            for (int mt = 0; mt < 2; mt++) {
                int r = (wm * 32 + mt * 16 + g8) * A_STR;
                Ah[mt][0] = ahi[r + ko];
                Ah[mt][1] = ahi[r + 8 * A_STR + ko];
                Ah[mt][2] = ahi[r + ko + 4];
                Ah[mt][3] = ahi[r + 8 * A_STR + ko + 4];
                Al[mt][0] = alo[r + ko];
                Al[mt][1] = alo[r + 8 * A_STR + ko];
                Al[mt][2] = alo[r + ko + 4];
                Al[mt][3] = alo[r + 8 * A_STR + ko + 4];
            }
#pragma unroll
            for (int nt = 0; nt < 4; nt++) {
                int nr = (wn * 32 + nt * 8 + g8) * B_STR;
                uint32_t Bh[2] = { bhi[nr + ko], bhi[nr + ko + 4] };
                uint32_t Bl[2] = { blo[nr + ko], blo[nr + ko + 4] };
#pragma unroll
                for (int mt = 0; mt < 2; mt++) {
                    mma16bf(acc[mt][nt], Ah[mt], Bh);
                    mma16bf(acc[mt][nt], Al[mt], Bh);
                    mma16bf(acc[mt][nt], Ah[mt], Bl);
                }
            }
        }
    }

#pragma unroll
    for (int mt = 0; mt < 2; mt++)
#pragma unroll
        for (int nt = 0; nt < 4; nt++) {
            int gr = m0 + wm * 32 + mt * 16 + g8;
            int gc = n0 + wn * 32 + nt * 8 + 2 * t4;
            float bz0 = bias[gc], bz1 = bias[gc + 1];
            float2 v0 = make_float2(acc[mt][nt][0] + bz0, acc[mt][nt][1] + bz1);
            float2 v1 = make_float2(acc[mt][nt][2] + bz0, acc[mt][nt][3] + bz1);
            *(float2*)&C[(size_t)gr * G4 + gc] = v0;
            *(float2*)&C[(size_t)(gr + 8) * G4 + gc] = v1;
        }
}

// ---------------- persistent recurrent layer: EXACT R13 inner loop ---------
// 256 thr, 8 warps, warp tile m16n16, 8 chunks of 64 kp, 2 syncs/chunk,
// single accumulator set, single h staging buffer. Tree barrier + pre-barrier
// G prefetch. Epilogue: layer0 -> bf16 planes, layer1 -> fp32 out.
#define SM_UHI 0                          // [32][516]
#define SM_ULO 16512
#define SM_HHI 33024                      // [64][68]
#define SM_HLO 37376
#define SM_CS  41728                      // [64][34] f32
#define SM_TOT (43904 * 4)                // 175616 bytes
#define USTR 516
#define HSTR 68
#define CSTR 34

__global__ __launch_bounds__(256, 1) void lstm_mma(
    const float* __restrict__ Gbase,
    const uint32_t* __restrict__ Ubhi,
    const uint32_t* __restrict__ Ublo,
    const float* __restrict__ h0,
    const float* __restrict__ c0,
    uint32_t* __restrict__ hpp,
    uint32_t* __restrict__ hseqhi,        // layer0: bf16 plane out (else null)
    uint32_t* __restrict__ hseqlo,
    float* __restrict__ seq_out,          // layer1: fp32 out at [b*T*H + t*H + u]
    float* hT, float* cT)
{
    extern __shared__ uint32_t sm[];
    float* smf = (float*)sm;
    int tid = threadIdx.x;
    int lane = tid & 31, wid = tid >> 5;
    int wm = wid & 3, wn = wid >> 2;
    int t4 = lane & 3, g8 = lane >> 2;
    int blk = blockIdx.x;

    // ---- load U slice (once) ----
    {
        const float4* shi = (const float4*)(Ubhi + (size_t)blk * 32 * 512);
        const float4* slo = (const float4*)(Ublo + (size_t)blk * 32 * 512);
#pragma unroll
        for (int i = 0; i < 16; i++) {
            int f = tid + i * 256;
            int n = f >> 7, c = f & 127;
            *(float4*)&sm[SM_UHI + n * USTR + c * 4] = shi[f];
            *(float4*)&sm[SM_ULO + n * USTR + c * 4] = slo[f];
        }
    }

    // ---- init h planes (ping 0) ----
    for (int slot = blk * 256 + tid; slot < BB * 512; slot += NBLK * 256) {
        int b = slot >> 9, kp = slot & 511;
        uint32_t hi, lo;
        pack_hl(h0[b * HH + 2 * kp], h0[b * HH + 2 * kp + 1], hi, lo);
        hpp[0 * 65536 + 0 * 32768 + slot] = hi;
        hpp[1 * 65536 + 0 * 32768 + slot] = lo;
    }
    int ju = tid & 3, bg = tid >> 2;
    int u0g = blk * 8 + 2 * ju;
    int kp_own = blk * 4 + ju;
    float cE = c0[bg * HH + u0g], cO = c0[bg * HH + u0g + 1];

    // staging map: 4 float4 per plane per chunk (64 rows x 16 float4)
    int srow[4], scol[4];
#pragma unroll
    for (int j = 0; j < 4; j++) {
        int f = tid + j * 256;
        srow[j] = f >> 4;
        scol[j] = f & 15;
    }
    int r0 = 16 * wm + g8;

    for (int t = 0; t < TT; t++) {
        // ---- prefetch G accumulators BEFORE barrier ----
        const float* Gt = Gbase + (size_t)t * BB * G4;
        float acc[2][4];
#pragma unroll
        for (int nt = 0; nt < 2; nt++) {
            int gcol = (2 * wn + nt) * HH + blk * 8 + 2 * t4;
            float2 v0 = *(const float2*)&Gt[(size_t)r0 * G4 + gcol];
            float2 v1 = *(const float2*)&Gt[(size_t)(r0 + 8) * G4 + gcol];
            acc[nt][0] = v0.x; acc[nt][1] = v0.y;
            acc[nt][2] = v1.x; acc[nt][3] = v1.y;
        }

        grid_barrier();

        const uint32_t* hin_hi = hpp + 0 * 65536 + (t & 1) * 32768;
        const uint32_t* hin_lo = hpp + 1 * 65536 + (t & 1) * 32768;
        uint32_t* hout_hi = hpp + 0 * 65536 + ((t + 1) & 1) * 32768;
        uint32_t* hout_lo = hpp + 1 * 65536 + ((t + 1) & 1) * 32768;

        // prefetch chunk 0
        float4 rhi[4], rlo[4];
#pragma unroll
        for (int j = 0; j < 4; j++) {
            rhi[j] = ((const float4*)(hin_hi + srow[j] * 512))[scol[j]];
            rlo[j] = ((const float4*)(hin_lo + srow[j] * 512))[scol[j]];
        }

        for (int kc = 0; kc < 8; kc++) {
#pragma unroll
            for (int j = 0; j < 4; j++) {
                *(float4*)&sm[SM_HHI + srow[j] * HSTR + scol[j] * 4] = rhi[j];
                *(float4*)&sm[SM_HLO + srow[j] * HSTR + scol[j] * 4] = rlo[j];
            }
            __syncthreads();
            // prefetch next chunk (chunk stride = 64 u32)
            if (kc < 7) {
#pragma unroll
                for (int j = 0; j < 4; j++) {
                    rhi[j] = ((const float4*)(hin_hi + srow[j] * 512 + (kc + 1) * 64))[scol[j]];
                    rlo[j] = ((const float4*)(hin_lo + srow[j] * 512 + (kc + 1) * 64))[scol[j]];
                }
            }
            // 8 x k16 mma
#pragma unroll
            for (int kk = 0; kk < 8; kk++) {
                int ko = kk * 8 + t4;
                int ku = kc * 64 + ko;
                uint32_t Ah[4], Al[4];
                Ah[0] = sm[SM_HHI + r0 * HSTR + ko];
                Ah[1] = sm[SM_HHI + (r0 + 8) * HSTR + ko];
                Ah[2] = sm[SM_HHI + r0 * HSTR + ko + 4];
                Ah[3] = sm[SM_HHI + (r0 + 8) * HSTR + ko + 4];
                Al[0] = sm[SM_HLO + r0 * HSTR + ko];
                Al[1] = sm[SM_HLO + (r0 + 8) * HSTR + ko];
                Al[2] = sm[SM_HLO + r0 * HSTR + ko + 4];
                Al[3] = sm[SM_HLO + (r0 + 8) * HSTR + ko + 4];
#pragma unroll
                for (int nt = 0; nt < 2; nt++) {
                    int n = 16 * wn + nt * 8 + g8;
                    uint32_t Bh[2] = { sm[SM_UHI + n * USTR + ku], sm[SM_UHI + n * USTR + ku + 4] };
                    uint32_t Bl[2] = { sm[SM_ULO + n * USTR + ku], sm[SM_ULO + n * USTR + ku + 4] };
                    mma16bf(acc[nt], Ah, Bh);
                    mma16bf(acc[nt], Al, Bh);
                    mma16bf(acc[nt], Ah, Bl);
                }
            }
            __syncthreads();
        }

        // ---- C frags -> smem ----
#pragma unroll
        for (int nt = 0; nt < 2; nt++) {
            int nc = 16 * wn + nt * 8 + 2 * t4;
            smf[SM_CS + r0 * CSTR + nc]           = acc[nt][0];
            smf[SM_CS + r0 * CSTR + nc + 1]       = acc[nt][1];
            smf[SM_CS + (r0 + 8) * CSTR + nc]     = acc[nt][2];
            smf[SM_CS + (r0 + 8) * CSTR + nc + 1] = acc[nt][3];
        }
        __syncthreads();

        // ---- elementwise: thread = (bg, ju) ----
        {
            const float* crow = smf + SM_CS + bg * CSTR;
            float2 gi = *(const float2*)&crow[0 * 8 + 2 * ju];
            float2 gf = *(const float2*)&crow[1 * 8 + 2 * ju];
            float2 gg = *(const float2*)&crow[2 * 8 + 2 * ju];
            float2 go = *(const float2*)&crow[3 * 8 + 2 * ju];

            float cnE = d_sigmoid(gf.x) * cE + d_sigmoid(gi.x) * d_tanh(gg.x);
            float cnO = d_sigmoid(gf.y) * cO + d_sigmoid(gi.y) * d_tanh(gg.y);
            float hnE = d_sigmoid(go.x) * d_tanh(cnE);
            float hnO = d_sigmoid(go.y) * d_tanh(cnO);
            cE = cnE; cO = cnO;

            uint32_t hi, lo;
            pack_hl(hnE, hnO, hi, lo);
            int slot = bg * 512 + kp_own;
            hout_hi[slot] = hi;
            hout_lo[slot] = lo;

            if (hseqhi) {
                size_t r = ((size_t)t * BB + bg) * 512 + kp_own;
                hseqhi[r] = hi;
                hseqlo[r] = lo;
            } else {
                *(float2*)&seq_out[((size_t)bg * TT + t) * HH + u0g] =
                    make_float2(hnE, hnO);
                if (t == TT - 1 && hT) {
                    int hidx = bg * HH + u0g;
                    *(float2*)&hT[hidx] = make_float2(hnE, hnO);
                    *(float2*)&cT[hidx] = make_float2(cnE, cnO);
                }
            }
        }
        // next grid_barrier's __syncthreads protects Cs reuse
    }
}

// ---------------- launch ----------------
extern "C" void kernel_launch(void* const* d_in, const int* in_sizes, int n_in,
                              void* d_out, int out_size)
{
    const float* X  = (const float*)d_in[0];
    const float* h0 = (const float*)d_in[1];
    const float* c0 = (const float*)d_in[2];
    const float* W0 = (const float*)d_in[3];
    const float* U0 = (const float*)d_in[4];
    const float* b0 = (const float*)d_in[5];
    const float* W1 = (const float*)d_in[6];
    const float* U1 = (const float*)d_in[7];
    const float* b1 = (const float*)d_in[8];
    float* out = (float*)d_out;

    float *G;
    uint32_t *Uh0, *Ul0, *Uh1, *Ul1, *hbf;
    uint32_t *Xhi, *Xlo, *Wh0, *Wl0, *Wh1, *Wl1, *Hshi, *Hslo;
    cudaGetSymbolAddress((void**)&G,    g_G);
    cudaGetSymbolAddress((void**)&Uh0,  g_Ubhi0);
    cudaGetSymbolAddress((void**)&Ul0,  g_Ublo0);
    cudaGetSymbolAddress((void**)&Uh1,  g_Ubhi1);
    cudaGetSymbolAddress((void**)&Ul1,  g_Ublo1);
    cudaGetSymbolAddress((void**)&hbf,  g_hbf);
    cudaGetSymbolAddress((void**)&Xhi,  g_Xhi);
    cudaGetSymbolAddress((void**)&Xlo,  g_Xlo);
    cudaGetSymbolAddress((void**)&Wh0,  g_Whi0);
    cudaGetSymbolAddress((void**)&Wl0,  g_Wlo0);
    cudaGetSymbolAddress((void**)&Wh1,  g_Whi1);
    cudaGetSymbolAddress((void**)&Wl1,  g_Wlo1);
    cudaGetSymbolAddress((void**)&Hshi, g_Hshi);
    cudaGetSymbolAddress((void**)&Hslo, g_Hslo);

    cudaFuncSetAttribute(gemm_bf16, cudaFuncAttributeMaxDynamicSharedMemorySize, GSMEM);
    cudaFuncSetAttribute(lstm_mma,  cudaFuncAttributeMaxDynamicSharedMemorySize, SM_TOT);

    packUbf16<<<(NBLK * 32 * 512) / 256, 256>>>(U0, Uh0, Ul0);
    packUbf16<<<(NBLK * 32 * 512) / 256, 256>>>(U1, Uh1, Ul1);
    packRows<<<(BB * TT * 256) / 256, 256>>>(X, Xhi, Xlo, BB * TT * 256);
    packW<<<(G4 * 256) / 256, 256>>>(W0, Wh0, Wl0, 256);
    packW<<<(G4 * 512) / 256, 256>>>(W1, Wh1, Wl1, 512);

    dim3 ggrid(G4 / 64, (TT * BB) / 128);   // (64, 256)

    bool wantHC = (size_t)out_size >= (size_t)BB * TT * HH + 2ull * BB * HH;
    float* hT = wantHC ? out + (size_t)BB * TT * HH : nullptr;
    float* cT = wantHC ? hT + (size_t)BB * HH : nullptr;

    // ---- layer 0 ----
    gemm_bf16<<<ggrid, 256, GSMEM>>>(Xhi, Xlo, Wh0, Wl0, b0, G, 256, 256, 0);
    lstm_mma<<<NBLK, 256, SM_TOT>>>(G, Uh0, Ul0, h0, c0, hbf,
                                    Hshi, Hslo, nullptr,
                                    nullptr, nullptr);

    // ---- layer 1 ----
    gemm_bf16<<<ggrid, 256, GSMEM>>>(Hshi, Hslo, Wh1, Wl1, b1, G, 512, 512, 1);
    lstm_mma<<<NBLK, 256, SM_TOT>>>(G, Uh1, Ul1,
                                    h0 + (size_t)BB * HH, c0 + (size_t)BB * HH,
                                    hbf,
                                    nullptr, nullptr, out,
                                    hT, cT);
}

// round 16
// speedup vs baseline: 1.1525x; 1.0768x over previous
#include <cuda_runtime.h>
#include <cuda_bf16.h>
#include <math.h>
#include <stdint.h>

#define BB 64      // batch
#define TT 512     // seq len
#define DD 512     // input size
#define HH 1024    // hidden
#define G4 4096    // 4*HH
#define NBLK 128   // persistent blocks (1/SM, co-resident)

// ---------------- scratch (static __device__, no allocs) ----------------
__device__ float g_G[(size_t)TT * BB * G4];
__device__ float g_hseq[(size_t)TT * BB * HH];
__device__ uint32_t g_Ubhi0[(size_t)NBLK * 32 * 512];  // [blk][n32][kp512]
__device__ uint32_t g_Ublo0[(size_t)NBLK * 32 * 512];
__device__ uint32_t g_Ubhi1[(size_t)NBLK * 32 * 512];
__device__ uint32_t g_Ublo1[(size_t)NBLK * 32 * 512];
__device__ uint32_t g_hbf[2 * 2 * BB * 512];           // [plane][ping][b][kp]

// ---------------- two-level tree grid barrier (validated R13) ----------------
__device__ unsigned g_c1[16 * 32];
__device__ unsigned g_croot = 0;
__device__ volatile unsigned g_gen = 0;

__device__ __forceinline__ void grid_barrier() {
    __syncthreads();
    if (threadIdx.x == 0) {
        __threadfence();
        unsigned old = g_gen;
        unsigned grp = blockIdx.x >> 3;
        if (atomicAdd(&g_c1[grp * 32], 1u) == 7u) {
            g_c1[grp * 32] = 0;
            __threadfence();
            if (atomicAdd(&g_croot, 1u) == 15u) {
                g_croot = 0;
                __threadfence();
                g_gen = old + 1;
            }
        }
        while (g_gen == old) { }
        __threadfence();
    }
    __syncthreads();
}

__device__ __forceinline__ float d_sigmoid(float x) { return 1.0f / (1.0f + expf(-x)); }
__device__ __forceinline__ float d_tanh(float x)    { return 1.0f - 2.0f / (expf(2.0f * x) + 1.0f); }

// ---------------- bf16 / ldmatrix helpers ----------------
__device__ __forceinline__ void mma16bf(float* c, const uint32_t* a, const uint32_t* b) {
    asm volatile("mma.sync.aligned.m16n8k16.row.col.f32.bf16.bf16.f32 "
        "{%0,%1,%2,%3}, {%4,%5,%6,%7}, {%8,%9}, {%0,%1,%2,%3};\n"
        : "+f"(c[0]), "+f"(c[1]), "+f"(c[2]), "+f"(c[3])
        : "r"(a[0]), "r"(a[1]), "r"(a[2]), "r"(a[3]), "r"(b[0]), "r"(b[1]));
}
__device__ __forceinline__ void ldsm_x4(uint32_t* r, uint32_t addr) {
    asm volatile("ldmatrix.sync.aligned.m8n8.x4.shared.b16 {%0,%1,%2,%3}, [%4];"
        : "=r"(r[0]), "=r"(r[1]), "=r"(r[2]), "=r"(r[3]) : "r"(addr));
}
__device__ __forceinline__ void ldsm_x2(uint32_t* r, uint32_t addr) {
    asm volatile("ldmatrix.sync.aligned.m8n8.x2.shared.b16 {%0,%1}, [%2];"
        : "=r"(r[0]), "=r"(r[1]) : "r"(addr));
}
__device__ __forceinline__ void pack_hl(float a, float b, uint32_t& hi, uint32_t& lo) {
    __nv_bfloat16 ah = __float2bfloat16_rn(a);
    __nv_bfloat16 bh = __float2bfloat16_rn(b);
    __nv_bfloat16 al = __float2bfloat16_rn(a - __bfloat162float(ah));
    __nv_bfloat16 bl = __float2bfloat16_rn(b - __bfloat162float(bh));
    hi = (uint32_t)*(uint16_t*)&ah | ((uint32_t)*(uint16_t*)&bh << 16);
    lo = (uint32_t)*(uint16_t*)&al | ((uint32_t)*(uint16_t*)&bl << 16);
}

// ---------------- U pack (validated) ----------------
__global__ void packUbf16(const float* __restrict__ U,
                          uint32_t* __restrict__ Uhi, uint32_t* __restrict__ Ulo) {
    int e = blockIdx.x * blockDim.x + threadIdx.x;
    if (e >= NBLK * 32 * 512) return;
    int kp  = e & 511;
    int n   = (e >> 9) & 31;
    int blk = e >> 14;
    int g = n >> 3, u = n & 7;
    int col = g * HH + blk * 8 + u;
    uint32_t hi, lo;
    pack_hl(U[(size_t)(2 * kp) * G4 + col], U[(size_t)(2 * kp + 1) * G4 + col], hi, lo);
    Uhi[e] = hi; Ulo[e] = lo;
}

// ---------------- bf16x3 big GEMM (validated R8/R13, fp32 inputs) ----------
#define KTG 32
#define A_STR 20
#define B_STR 20
#define A_PL (128 * A_STR)
#define B_PL (64 * B_STR)
#define GBUF (2 * A_PL + 2 * B_PL)
#define GSMEM (2 * GBUF * 4)

__global__ __launch_bounds__(256, 2) void gemm_bf16(
    const float* __restrict__ A, const float* __restrict__ W,
    const float* __restrict__ bias, float* __restrict__ C, int K, int mode)
{
    extern __shared__ uint32_t sm[];
    int tid = threadIdx.x;
    int lane = tid & 31, wid = tid >> 5;
    int wm = wid & 3, wn = wid >> 2;
    int t4 = lane & 3, g8 = lane >> 2;
    int m0 = blockIdx.y * 128, n0 = blockIdx.x * 64;

    const float* pA[4];
    int amL[4], akq[4];
#pragma unroll
    for (int j = 0; j < 4; j++) {
        int idx = tid + j * 256;
        int m = idx >> 3;
        int kq = idx & 7;
        amL[j] = m; akq[j] = kq;
        int gm = m0 + m;
        size_t row = (mode == 0) ? (size_t)(gm & 63) * TT + (gm >> 6) : (size_t)gm;
        pA[j] = A + row * K + 4 * kq;
    }
    int nB = tid & 63, kg = tid >> 6;
    const float* pB = W + (size_t)(8 * kg) * G4 + n0 + nB;

    float4 fa[4];
    float fbr[8];
#pragma unroll
    for (int j = 0; j < 4; j++) fa[j] = *(const float4*)pA[j];
#pragma unroll
    for (int s = 0; s < 8; s++) fbr[s] = pB[(size_t)s * G4];

    float acc[2][4][4];
#pragma unroll
    for (int mt = 0; mt < 2; mt++)
#pragma unroll
        for (int nt = 0; nt < 4; nt++)
#pragma unroll
            for (int i = 0; i < 4; i++) acc[mt][nt][i] = 0.0f;

    int nIter = K / KTG;
    for (int it = 0; it < nIter; it++) {
        uint32_t* base = sm + (it & 1) * GBUF;
        uint32_t* ahi = base;
        uint32_t* alo = base + A_PL;
        uint32_t* bhi = base + 2 * A_PL;
        uint32_t* blo = bhi + B_PL;

#pragma unroll
        for (int j = 0; j < 4; j++) {
            uint32_t h0, l0, h1, l1;
            pack_hl(fa[j].x, fa[j].y, h0, l0);
            pack_hl(fa[j].z, fa[j].w, h1, l1);
            int off = amL[j] * A_STR + 2 * akq[j];
            ahi[off] = h0; ahi[off + 1] = h1;
            alo[off] = l0; alo[off + 1] = l1;
        }
        {
            uint32_t h[4], l[4];
#pragma unroll
            for (int p = 0; p < 4; p++)
                pack_hl(fbr[2 * p], fbr[2 * p + 1], h[p], l[p]);
            int off = nB * B_STR + 4 * kg;
            *(uint4*)&bhi[off] = make_uint4(h[0], h[1], h[2], h[3]);
            *(uint4*)&blo[off] = make_uint4(l[0], l[1], l[2], l[3]);
        }
        __syncthreads();

        if (it + 1 < nIter) {
#pragma unroll
            for (int j = 0; j < 4; j++) { pA[j] += KTG; fa[j] = *(const float4*)pA[j]; }
            pB += (size_t)KTG * G4;
#pragma unroll
            for (int s = 0; s < 8; s++) fbr[s] = pB[(size_t)s * G4];
        }

#pragma unroll
        for (int ks = 0; ks < 2; ks++) {
            int ko = ks * 8 + t4;
            uint32_t Ah[2][4], Al[2][4];
#pragma unroll
            for (int mt = 0; mt < 2; mt++) {
                int r = (wm * 32 + mt * 16 + g8) * A_STR;
                Ah[mt][0] = ahi[r + ko];
                Ah[mt][1] = ahi[r + 8 * A_STR + ko];
                Ah[mt][2] = ahi[r + ko + 4];
                Ah[mt][3] = ahi[r + 8 * A_STR + ko + 4];
                Al[mt][0] = alo[r + ko];
                Al[mt][1] = alo[r + 8 * A_STR + ko];
                Al[mt][2] = alo[r + ko + 4];
                Al[mt][3] = alo[r + 8 * A_STR + ko + 4];
            }
#pragma unroll
            for (int nt = 0; nt < 4; nt++) {
                int nr = (wn * 32 + nt * 8 + g8) * B_STR;
                uint32_t Bh[2] = { bhi[nr + ko], bhi[nr + ko + 4] };
                uint32_t Bl[2] = { blo[nr + ko], blo[nr + ko + 4] };
#pragma unroll
                for (int mt = 0; mt < 2; mt++) {
                    mma16bf(acc[mt][nt], Ah[mt], Bh);
                    mma16bf(acc[mt][nt], Al[mt], Bh);
                    mma16bf(acc[mt][nt], Ah[mt], Bl);
                }
            }
        }
    }

#pragma unroll
    for (int mt = 0; mt < 2; mt++)
#pragma unroll
        for (int nt = 0; nt < 4; nt++) {
            int gr = m0 + wm * 32 + mt * 16 + g8;
            int gc = n0 + wn * 32 + nt * 8 + 2 * t4;
            float bz0 = bias[gc], bz1 = bias[gc + 1];
            float2 v0 = make_float2(acc[mt][nt][0] + bz0, acc[mt][nt][1] + bz1);
            float2 v1 = make_float2(acc[mt][nt][2] + bz0, acc[mt][nt][3] + bz1);
            *(float2*)&C[(size_t)gr * G4 + gc] = v0;
            *(float2*)&C[(size_t)(gr + 8) * G4 + gc] = v1;
        }
}

// ---------------- persistent recurrent layer: R13 + ldmatrix frags ---------
// 256 thr, 8 warps, warp tile m16n16, 8 chunks of 64 kp, 2 syncs/chunk.
// Fragment loads via ldmatrix (bit-identical register contents to R13).
#define SM_UHI 0                          // [32][516]
#define SM_ULO 16512
#define SM_HHI 33024                      // [64][68]
#define SM_HLO 37376
#define SM_CS  41728                      // [64][34] f32
#define SM_TOT (43904 * 4)                // 175616 bytes
#define USTR 516
#define HSTR 68
#define CSTR 34

__global__ __launch_bounds__(256, 1) void lstm_mma(
    const float* __restrict__ Gbase,
    const uint32_t* __restrict__ Ubhi,
    const uint32_t* __restrict__ Ublo,
    const float* __restrict__ h0,
    const float* __restrict__ c0,
    uint32_t* __restrict__ hpp,
    float* __restrict__ seq_out, int t_str, int b_str,
    float* hT, float* cT)
{
    extern __shared__ uint32_t sm[];
    float* smf = (float*)sm;
    int tid = threadIdx.x;
    int lane = tid & 31, wid = tid >> 5;
    int wm = wid & 3, wn = wid >> 2;
    int t4 = lane & 3, g8 = lane >> 2;
    int blk = blockIdx.x;

    // ---- load U slice (once) ----
    {
        const float4* shi = (const float4*)(Ubhi + (size_t)blk * 32 * 512);
        const float4* slo = (const float4*)(Ublo + (size_t)blk * 32 * 512);
#pragma unroll
        for (int i = 0; i < 16; i++) {
            int f = tid + i * 256;
            int n = f >> 7, c = f & 127;
            *(float4*)&sm[SM_UHI + n * USTR + c * 4] = shi[f];
            *(float4*)&sm[SM_ULO + n * USTR + c * 4] = slo[f];
        }
    }

    // ---- init h planes (ping 0) ----
    for (int slot = blk * 256 + tid; slot < BB * 512; slot += NBLK * 256) {
        int b = slot >> 9, kp = slot & 511;
        uint32_t hi, lo;
        pack_hl(h0[b * HH + 2 * kp], h0[b * HH + 2 * kp + 1], hi, lo);
        hpp[0 * 65536 + 0 * 32768 + slot] = hi;
        hpp[1 * 65536 + 0 * 32768 + slot] = lo;
    }
    int ju = tid & 3, bg = tid >> 2;
    int u0g = blk * 8 + 2 * ju;
    int kp_own = blk * 4 + ju;
    float cE = c0[bg * HH + u0g], cO = c0[bg * HH + u0g + 1];

    // staging map: 4 float4 per plane per chunk (64 rows x 16 float4)
    int srow[4], scol[4];
#pragma unroll
    for (int j = 0; j < 4; j++) {
        int f = tid + j * 256;
        srow[j] = f >> 4;
        scol[j] = f & 15;
    }
    int r0 = 16 * wm + g8;

    // ---- ldmatrix per-lane addresses (bytes, shared space) ----
    uint32_t smbase = (uint32_t)__cvta_generic_to_shared(sm);
    int l7 = lane & 7, l8 = (lane >> 3) & 1, l16 = (lane >> 4) & 1;
    uint32_t aRow = (uint32_t)(16 * wm + l7 + 8 * l8);
    uint32_t aAddrHi = smbase + (SM_HHI + aRow * HSTR) * 4 + l16 * 16;
    uint32_t aAddrLo = smbase + (SM_HLO + aRow * HSTR) * 4 + l16 * 16;
    uint32_t bRow0 = (uint32_t)(16 * wn + l7);
    uint32_t bRow1 = (uint32_t)(16 * wn + 8 + l7);
    uint32_t bAddrHi0 = smbase + (SM_UHI + bRow0 * USTR) * 4 + l8 * 16;
    uint32_t bAddrLo0 = smbase + (SM_ULO + bRow0 * USTR) * 4 + l8 * 16;
    uint32_t bAddrHi1 = smbase + (SM_UHI + bRow1 * USTR) * 4 + l8 * 16;
    uint32_t bAddrLo1 = smbase + (SM_ULO + bRow1 * USTR) * 4 + l8 * 16;

    for (int t = 0; t < TT; t++) {
        // ---- prefetch G accumulators BEFORE barrier ----
        const float* Gt = Gbase + (size_t)t * BB * G4;
        float acc[2][4];
#pragma unroll
        for (int nt = 0; nt < 2; nt++) {
            int gcol = (2 * wn + nt) * HH + blk * 8 + 2 * t4;
            float2 v0 = *(const float2*)&Gt[(size_t)r0 * G4 + gcol];
            float2 v1 = *(const float2*)&Gt[(size_t)(r0 + 8) * G4 + gcol];
            acc[nt][0] = v0.x; acc[nt][1] = v0.y;
            acc[nt][2] = v1.x; acc[nt][3] = v1.y;
        }

        grid_barrier();

        const uint32_t* hin_hi = hpp + 0 * 65536 + (t & 1) * 32768;
        const uint32_t* hin_lo = hpp + 1 * 65536 + (t & 1) * 32768;
        uint32_t* hout_hi = hpp + 0 * 65536 + ((t + 1) & 1) * 32768;
        uint32_t* hout_lo = hpp + 1 * 65536 + ((t + 1) & 1) * 32768;

        // prefetch chunk 0
        float4 rhi[4], rlo[4];
#pragma unroll
        for (int j = 0; j < 4; j++) {
            rhi[j] = ((const float4*)(hin_hi + srow[j] * 512))[scol[j]];
            rlo[j] = ((const float4*)(hin_lo + srow[j] * 512))[scol[j]];
        }

        for (int kc = 0; kc < 8; kc++) {
#pragma unroll
            for (int j = 0; j < 4; j++) {
                *(float4*)&sm[SM_HHI + srow[j] * HSTR + scol[j] * 4] = rhi[j];
                *(float4*)&sm[SM_HLO + srow[j] * HSTR + scol[j] * 4] = rlo[j];
            }
            __syncthreads();
            // prefetch next chunk (chunk stride = 64 u32)
            if (kc < 7) {
#pragma unroll
                for (int j = 0; j < 4; j++) {
                    rhi[j] = ((const float4*)(hin_hi + srow[j] * 512 + (kc + 1) * 64))[scol[j]];
                    rlo[j] = ((const float4*)(hin_lo + srow[j] * 512 + (kc + 1) * 64))[scol[j]];
                }
            }
            // 8 x k16 mma, frags via ldmatrix
#pragma unroll
            for (int kk = 0; kk < 8; kk++) {
                uint32_t colA = (uint32_t)(kk * 32);
                uint32_t colB = (uint32_t)(kc * 256 + kk * 32);
                uint32_t Ah[4], Al[4];
                ldsm_x4(Ah, aAddrHi + colA);
                ldsm_x4(Al, aAddrLo + colA);
#pragma unroll
                for (int nt = 0; nt < 2; nt++) {
                    uint32_t Bh[2], Bl[2];
                    ldsm_x2(Bh, (nt ? bAddrHi1 : bAddrHi0) + colB);
                    ldsm_x2(Bl, (nt ? bAddrLo1 : bAddrLo0) + colB);
                    mma16bf(acc[nt], Ah, Bh);
                    mma16bf(acc[nt], Al, Bh);
                    mma16bf(acc[nt], Ah, Bl);
                }
            }
            __syncthreads();
        }

        // ---- C frags -> smem ----
#pragma unroll
        for (int nt = 0; nt < 2; nt++) {
            int nc = 16 * wn + nt * 8 + 2 * t4;
            smf[SM_CS + r0 * CSTR + nc]           = acc[nt][0];
            smf[SM_CS + r0 * CSTR + nc + 1]       = acc[nt][1];
            smf[SM_CS + (r0 + 8) * CSTR + nc]     = acc[nt][2];
            smf[SM_CS + (r0 + 8) * CSTR + nc + 1] = acc[nt][3];
        }
        __syncthreads();

        // ---- elementwise: thread = (bg, ju) ----
        {
            const float* crow = smf + SM_CS + bg * CSTR;
            float2 gi = *(const float2*)&crow[0 * 8 + 2 * ju];
            float2 gf = *(const float2*)&crow[1 * 8 + 2 * ju];
            float2 gg = *(const float2*)&crow[2 * 8 + 2 * ju];
            float2 go = *(const float2*)&crow[3 * 8 + 2 * ju];

            float cnE = d_sigmoid(gf.x) * cE + d_sigmoid(gi.x) * d_tanh(gg.x);
            float cnO = d_sigmoid(gf.y) * cO + d_sigmoid(gi.y) * d_tanh(gg.y);
            float hnE = d_sigmoid(go.x) * d_tanh(cnE);
            float hnO = d_sigmoid(go.y) * d_tanh(cnO);
            cE = cnE; cO = cnO;

            *(float2*)&seq_out[(size_t)t * t_str + (size_t)bg * b_str + u0g] =
                make_float2(hnE, hnO);
            uint32_t hi, lo;
            pack_hl(hnE, hnO, hi, lo);
            int slot = bg * 512 + kp_own;
            hout_hi[slot] = hi;
            hout_lo[slot] = lo;

            if (t == TT - 1 && hT) {
                int hidx = bg * HH + u0g;
                *(float2*)&hT[hidx] = make_float2(hnE, hnO);
                *(float2*)&cT[hidx] = make_float2(cnE, cnO);
            }
        }
        // next grid_barrier's __syncthreads protects Cs reuse
    }
}

// ---------------- launch ----------------
extern "C" void kernel_launch(void* const* d_in, const int* in_sizes, int n_in,
                              void* d_out, int out_size)
{
    const float* X  = (const float*)d_in[0];
    const float* h0 = (const float*)d_in[1];
    const float* c0 = (const float*)d_in[2];
    const float* W0 = (const float*)d_in[3];
    const float* U0 = (const float*)d_in[4];
    const float* b0 = (const float*)d_in[5];
    const float* W1 = (const float*)d_in[6];
    const float* U1 = (const float*)d_in[7];
    const float* b1 = (const float*)d_in[8];
    float* out = (float*)d_out;

    float *G, *hseq;
    uint32_t *Uh0, *Ul0, *Uh1, *Ul1, *hbf;
    cudaGetSymbolAddress((void**)&G,    g_G);
    cudaGetSymbolAddress((void**)&hseq, g_hseq);
    cudaGetSymbolAddress((void**)&Uh0,  g_Ubhi0);
    cudaGetSymbolAddress((void**)&Ul0,  g_Ublo0);
    cudaGetSymbolAddress((void**)&Uh1,  g_Ubhi1);
    cudaGetSymbolAddress((void**)&Ul1,  g_Ublo1);
    cudaGetSymbolAddress((void**)&hbf,  g_hbf);

    cudaFuncSetAttribute(gemm_bf16, cudaFuncAttributeMaxDynamicSharedMemorySize, GSMEM);
    cudaFuncSetAttribute(lstm_mma,  cudaFuncAttributeMaxDynamicSharedMemorySize, SM_TOT);

    packUbf16<<<(NBLK * 32 * 512) / 256, 256>>>(U0, Uh0, Ul0);
    packUbf16<<<(NBLK * 32 * 512) / 256, 256>>>(U1, Uh1, Ul1);

    dim3 ggrid(G4 / 64, (TT * BB) / 128);   // (64, 256)

    bool wantHC = (size_t)out_size >= (size_t)BB * TT * HH + 2ull * BB * HH;
    float* hT = wantHC ? out + (size_t)BB * TT * HH : nullptr;
    float* cT = wantHC ? hT + (size_t)BB * HH : nullptr;

    // ---- layer 0 ----
    gemm_bf16<<<ggrid, 256, GSMEM>>>(X, W0, b0, G, DD, 0);
    lstm_mma<<<NBLK, 256, SM_TOT>>>(G, Uh0, Ul0, h0, c0, hbf,
                                    hseq, BB * HH, HH,
                                    nullptr, nullptr);

    // ---- layer 1 ----
    gemm_bf16<<<ggrid, 256, GSMEM>>>(hseq, W1, b1, G, HH, 1);
    lstm_mma<<<NBLK, 256, SM_TOT>>>(G, Uh1, Ul1,
                                    h0 + (size_t)BB * HH, c0 + (size_t)BB * HH,
                                    hbf,
                                    out, HH, TT * HH,
                                    hT, cT);
}